// round 8
// baseline (speedup 1.0000x reference)
#include <cuda_runtime.h>
#include <math.h>
#include <stdint.h>

#define SEQ   4096
#define DIM   1024
#define OUTD  2048
#define SCALE 0.03125f   // 1/sqrt(1024)

#define PADW  36                        // 32 floats + 4 pad per smem row
#define ABUF  (256 * PADW * 4)          // 36864 B (A: 256 rows)
#define STAGEB (2 * ABUF)               // A + B per stage: 73728 B
#define SMEM_DYN (2 * STAGEB)           // 147456 B

// ---------------------------------------------------------------------------
// scratch (__device__ globals; no allocations allowed)
// ---------------------------------------------------------------------------
__device__ float g_x [(size_t)SEQ * DIM];          // x, tf32-rounded
__device__ float g_wt[(size_t)3 * DIM * DIM];      // W^T (Q,K,V), tf32-rounded
__device__ float g_q [(size_t)SEQ * DIM];          // tf32-rounded
__device__ float g_k [(size_t)SEQ * DIM];          // tf32-rounded
__device__ float g_vt[(size_t)DIM * SEQ];          // V^T [d][s], tf32-rounded
__device__ float g_s [(size_t)SEQ * SEQ];          // scores fp32
__device__ float g_p [(size_t)SEQ * SEQ];          // probs, tf32-rounded

// ---------------------------------------------------------------------------
// helpers
// ---------------------------------------------------------------------------
__device__ __forceinline__ uint32_t smem_u32(const void* p) {
    uint32_t a;
    asm("{ .reg .u64 t; cvta.to.shared.u64 t, %1; cvt.u32.u64 %0, t; }" : "=r"(a) : "l"(p));
    return a;
}
__device__ __forceinline__ float tf32r(float x) {
    uint32_t u;
    asm("cvt.rna.tf32.f32 %0, %1;" : "=r"(u) : "f"(x));
    return __uint_as_float(u);
}
__device__ __forceinline__ void cp16(uint32_t s, const float* g) {
    asm volatile("{ .reg .u64 gg; cvta.to.global.u64 gg, %1;"
                 "  cp.async.cg.shared.global [%0], [gg], 16; }"
                 :: "r"(s), "l"(g));
}
#define CP_COMMIT() asm volatile("cp.async.commit_group;" ::: "memory")
#define CP_WAIT1()  asm volatile("cp.async.wait_group 1;"  ::: "memory")

__device__ __forceinline__ void ldsm4(uint32_t& r0, uint32_t& r1, uint32_t& r2, uint32_t& r3,
                                      uint32_t addr) {
    asm volatile("ldmatrix.sync.aligned.m8n8.x4.shared.b16 {%0,%1,%2,%3}, [%4];"
                 : "=r"(r0), "=r"(r1), "=r"(r2), "=r"(r3) : "r"(addr));
}

__device__ __forceinline__ void mma8(float* d, const uint32_t* a, const uint32_t* b) {
    asm volatile(
        "mma.sync.aligned.m16n8k8.row.col.f32.tf32.tf32.f32 "
        "{%0,%1,%2,%3}, {%4,%5,%6,%7}, {%8,%9}, {%0,%1,%2,%3};"
        : "+f"(d[0]), "+f"(d[1]), "+f"(d[2]), "+f"(d[3])
        : "r"(a[0]), "r"(a[1]), "r"(a[2]), "r"(a[3]), "r"(b[0]), "r"(b[1]));
}

// ---------------------------------------------------------------------------
// mainloop (512 threads): acc[4][8][4] += A[256,K] * B[256,K]^T
// 16 warps = 4(m) x 4(n); warp tile 64x64; tf32 m16n8k8; ldmatrix frags;
// 2-stage cp.async (R6 structure).
// ---------------------------------------------------------------------------
__device__ __forceinline__ void gemm_mainloop(
    float (*acc)[8][4], char* smem,
    const float* __restrict__ Ag, int lda, int arow0,
    const float* __restrict__ Bg, int ldb, int brow0,
    int kbeg, int kend)
{
    const int tid  = threadIdx.x;
    const int wid  = tid >> 5, lane = tid & 31;
    const int wm   = (wid & 3) * 64;
    const int wn   = (wid >> 2) * 64;
    const uint32_t sA = smem_u32(smem);
    const int nch  = (kend - kbeg) >> 5;

    // ldmatrix per-lane base offsets (bytes, within stage)
    const uint32_t aoff = ((wm + (lane & 15)) * PADW + (lane >> 4) * 4) * 4;
    const uint32_t boff = ABUF +
        ((wn + (lane & 7) + ((lane >> 4) & 1) * 8) * PADW + ((lane >> 3) & 1) * 4) * 4;

    // loaders: 256 rows per operand, 2 threads/row, 4 cp16 each
    const int lm = tid >> 1;
    const int lq = (tid & 1) * 4;

#define ISSUE_CHUNK(stg, k0) do {                                              \
    uint32_t _st = sA + (stg) * STAGEB;                                        \
    _Pragma("unroll")                                                          \
    for (int q = 0; q < 4; q++)                                                \
        cp16(_st + (lm * PADW + (lq + q) * 4) * 4,                             \
             Ag + (size_t)(arow0 + lm) * lda + (k0) + (lq + q) * 4);           \
    _Pragma("unroll")                                                          \
    for (int q = 0; q < 4; q++)                                                \
        cp16(_st + ABUF + (lm * PADW + (lq + q) * 4) * 4,                      \
             Bg + (size_t)(brow0 + lm) * ldb + (k0) + (lq + q) * 4);           \
} while (0)

    ISSUE_CHUNK(0, kbeg);
    CP_COMMIT();
    if (nch > 1) ISSUE_CHUNK(1, kbeg + 32);
    CP_COMMIT();

    for (int c = 0; c < nch; c++) {
        CP_WAIT1();
        __syncthreads();
        const uint32_t sb = sA + (c & 1) * STAGEB;
#pragma unroll
        for (int ks = 0; ks < 4; ks++) {
            uint32_t af[4][4], bf[8][2];
#pragma unroll
            for (int mt = 0; mt < 4; mt++)
                ldsm4(af[mt][0], af[mt][1], af[mt][2], af[mt][3],
                      sb + aoff + mt * (16 * PADW * 4) + ks * 32);
#pragma unroll
            for (int n2 = 0; n2 < 4; n2++)
                ldsm4(bf[2 * n2][0], bf[2 * n2][1], bf[2 * n2 + 1][0], bf[2 * n2 + 1][1],
                      sb + boff + n2 * (16 * PADW * 4) + ks * 32);
#pragma unroll
            for (int mt = 0; mt < 4; mt++)
#pragma unroll
                for (int nt = 0; nt < 8; nt++)
                    mma8(acc[mt][nt], af[mt], bf[nt]);
        }
        __syncthreads();
        if (c + 2 < nch) ISSUE_CHUNK(c & 1, kbeg + (c + 2) * 32);
        CP_COMMIT();
    }
#undef ISSUE_CHUNK
}

#define GEMM_THREAD_COORDS()                                     \
    const int tid = threadIdx.x;                                 \
    const int wid = tid >> 5, lane = tid & 31;                   \
    const int wm = (wid & 3) * 64, wn = (wid >> 2) * 64;         \
    const int r = lane >> 2, cc = lane & 3;

#define ZERO_ACC(acc)                                            \
    float acc[4][8][4];                                          \
    _Pragma("unroll")                                            \
    for (int i = 0; i < 4; i++)                                  \
        _Pragma("unroll")                                        \
        for (int j = 0; j < 8; j++)                              \
            _Pragma("unroll")                                    \
            for (int q = 0; q < 4; q++) acc[i][j][q] = 0.f;

// ---------------------------------------------------------------------------
// QKV: z=0: Q = x@Wq' + bq ; z=1: K ; z=2: V^T = Wvt @ x^T + bv(row)
// grid (64,1,3): z<2: bi=b>>2 (16 m-tiles of 256), bj=b&3 (4 n-tiles of 256)
//                z=2: bi=b>>4 (4 m-tiles over DIM), bj=b&15 (16 over SEQ)
// ---------------------------------------------------------------------------
__global__ __launch_bounds__(512, 1) void gemm_qkv_kernel(
    const float* __restrict__ bq, const float* __restrict__ bk, const float* __restrict__ bv)
{
    const int z = blockIdx.z;
    extern __shared__ char smem[];
    const int b = blockIdx.x;
    const int row0 = (z == 2 ? (b >> 4) : (b >> 2)) * 256;
    const int col0 = (z == 2 ? (b & 15) : (b & 3)) * 256;

    ZERO_ACC(acc);

    const float *Ag, *Bg, *bias;
    if (z == 0)      { Ag = g_x;                  Bg = g_wt;             bias = bq; }
    else if (z == 1) { Ag = g_x;                  Bg = g_wt + DIM * DIM; bias = bk; }
    else             { Ag = g_wt + 2 * DIM * DIM; Bg = g_x;              bias = bv; }

    gemm_mainloop(acc, smem, Ag, DIM, row0, Bg, DIM, col0, 0, DIM);

    GEMM_THREAD_COORDS();
    float* dst; size_t ld;
    if (z == 0)      { dst = g_q;  ld = DIM; }
    else if (z == 1) { dst = g_k;  ld = DIM; }
    else             { dst = g_vt; ld = SEQ; }

#pragma unroll
    for (int mt = 0; mt < 4; mt++)
#pragma unroll
        for (int h = 0; h < 2; h++) {
            int m = row0 + wm + mt * 16 + r + 8 * h;
            float brow = (z == 2) ? bias[m] : 0.f;
#pragma unroll
            for (int nt = 0; nt < 8; nt++) {
                int n = col0 + wn + nt * 8 + 2 * cc;
                float v0 = acc[mt][nt][2 * h + 0] + ((z == 2) ? brow : bias[n]);
                float v1 = acc[mt][nt][2 * h + 1] + ((z == 2) ? brow : bias[n + 1]);
                float2 w = make_float2(tf32r(v0), tf32r(v1));
                *(float2*)&dst[(size_t)m * ld + n] = w;
            }
        }
}

// ---------------------------------------------------------------------------
// scores: S = SCALE * Q K^T, tiles 256x256; kept iff bj >= bi (136 blocks)
// ---------------------------------------------------------------------------
__global__ __launch_bounds__(512, 1) void gemm_scores_kernel()
{
    int bi = 0, rem = blockIdx.x;
    while (rem >= 16 - bi) { rem -= 16 - bi; bi++; }
    const int bj = bi + rem;

    extern __shared__ char smem[];
    const int row0 = bi * 256, col0 = bj * 256;

    ZERO_ACC(acc);
    gemm_mainloop(acc, smem, g_q, DIM, row0, g_k, DIM, col0, 0, DIM);

    GEMM_THREAD_COORDS();
#pragma unroll
    for (int mt = 0; mt < 4; mt++)
#pragma unroll
        for (int h = 0; h < 2; h++) {
            int m = row0 + wm + mt * 16 + r + 8 * h;
#pragma unroll
            for (int nt = 0; nt < 8; nt++) {
                int n = col0 + wn + nt * 8 + 2 * cc;
                float2 w = make_float2(acc[mt][nt][2 * h] * SCALE,
                                       acc[mt][nt][2 * h + 1] * SCALE);
                *(float2*)&g_s[(size_t)m * SEQ + n] = w;
            }
        }
}

// ---------------------------------------------------------------------------
// softmax over j >= i; writes tf32-rounded probs, zero strip down to the
// 256-aligned tile base so PV can start k at the diagonal 256-tile.
// ---------------------------------------------------------------------------
__global__ __launch_bounds__(256) void softmax_kernel()
{
    const int i = blockIdx.x;
    const int t = threadIdx.x;
    const float* row = g_s + (size_t)i * SEQ;

    float vals[16];
    float m = -INFINITY;
#pragma unroll
    for (int c = 0; c < 16; c++) {
        int j = t + (c << 8);
        float v = (j >= i) ? row[j] : -INFINITY;
        vals[c] = v;
        m = fmaxf(m, v);
    }
    __shared__ float red[8];
#pragma unroll
    for (int o = 16; o > 0; o >>= 1) m = fmaxf(m, __shfl_xor_sync(0xffffffffu, m, o));
    if ((t & 31) == 0) red[t >> 5] = m;
    __syncthreads();
    float mm = red[0];
#pragma unroll
    for (int w = 1; w < 8; w++) mm = fmaxf(mm, red[w]);
    __syncthreads();

    float sum = 0.f;
#pragma unroll
    for (int c = 0; c < 16; c++) {
        float e = (vals[c] > -INFINITY) ? __expf(vals[c] - mm) : 0.f;
        vals[c] = e;
        sum += e;
    }
#pragma unroll
    for (int o = 16; o > 0; o >>= 1) sum += __shfl_xor_sync(0xffffffffu, sum, o);
    if ((t & 31) == 0) red[t >> 5] = sum;
    __syncthreads();
    float tot = 0.f;
#pragma unroll
    for (int w = 0; w < 8; w++) tot += red[w];
    const float inv = 1.0f / tot;

    const int rowstart = i & ~255;
    float* p = g_p + (size_t)i * SEQ;
#pragma unroll
    for (int c = 0; c < 16; c++) {
        int j = t + (c << 8);
        if (j >= i)             p[j] = tf32r(vals[c] * inv);
        else if (j >= rowstart) p[j] = 0.f;
    }
}

// ---------------------------------------------------------------------------
// PV: read = P @ V ; tiles 256x256; k starts at the diagonal 256-tile.
// grid (4, 16): row0 = y*256, col0 = x*256
// ---------------------------------------------------------------------------
__global__ __launch_bounds__(512, 1) void gemm_pv_kernel(float* __restrict__ out)
{
    extern __shared__ char smem[];
    const int row0 = blockIdx.y * 256, col0 = blockIdx.x * 256;

    ZERO_ACC(acc);
    gemm_mainloop(acc, smem, g_p, SEQ, row0, g_vt, SEQ, col0, row0, SEQ);

    GEMM_THREAD_COORDS();
#pragma unroll
    for (int mt = 0; mt < 4; mt++)
#pragma unroll
        for (int h = 0; h < 2; h++) {
            int m = row0 + wm + mt * 16 + r + 8 * h;
#pragma unroll
            for (int nt = 0; nt < 8; nt++) {
                int n = col0 + wn + nt * 8 + 2 * cc;
                float2 w = make_float2(acc[mt][nt][2 * h], acc[mt][nt][2 * h + 1]);
                *(float2*)&out[(size_t)m * OUTD + DIM + n] = w;
            }
        }
}

// ---------------------------------------------------------------------------
// conversions
// ---------------------------------------------------------------------------
__global__ __launch_bounds__(256) void conv_x_kernel(const float* __restrict__ x,
                                                     float* __restrict__ out)
{
    int idx = blockIdx.x * 256 + threadIdx.x;   // float4 index
    int r = idx >> 8;
    int c = (idx & 255) * 4;
    float4 v = *(const float4*)&x[(size_t)r * DIM + c];
    *(float4*)&out[(size_t)r * OUTD + c] = v;   // out[:, 0:1024] = x
    float4 w = make_float4(tf32r(v.x), tf32r(v.y), tf32r(v.z), tf32r(v.w));
    *(float4*)&g_x[(size_t)r * DIM + c] = w;
}

// transpose + tf32-round W [k][n] -> Wt [n][k] (slot z: 0=Q, 1=K, 2=V)
__global__ __launch_bounds__(256) void conv_w_kernel(const float* __restrict__ Wq,
                                                     const float* __restrict__ Wk,
                                                     const float* __restrict__ Wv)
{
    __shared__ float t[32][33];
    const int z = blockIdx.z;
    const float* W = (z == 0) ? Wq : (z == 1) ? Wk : Wv;
    const int n0 = blockIdx.x * 32, k0 = blockIdx.y * 32;
    const int tx = threadIdx.x & 31, ty = threadIdx.x >> 5;
#pragma unroll
    for (int i = 0; i < 4; i++) {
        int k = ty + i * 8;
        t[k][tx] = W[(size_t)(k0 + k) * DIM + n0 + tx];
    }
    __syncthreads();
    float* T = g_wt + (size_t)z * DIM * DIM;
#pragma unroll
    for (int i = 0; i < 4; i++) {
        int n = ty + i * 8;
        T[(size_t)(n0 + n) * DIM + k0 + tx] = tf32r(t[tx][n]);
    }
}

// ---------------------------------------------------------------------------
extern "C" void kernel_launch(void* const* d_in, const int* in_sizes, int n_in,
                              void* d_out, int out_size)
{
    const float* x  = (const float*)d_in[0];
    const float* Wk = (const float*)d_in[1];
    const float* bk = (const float*)d_in[2];
    const float* Wq = (const float*)d_in[3];
    const float* bq = (const float*)d_in[4];
    const float* Wv = (const float*)d_in[5];
    const float* bv = (const float*)d_in[6];
    float* out = (float*)d_out;

    cudaFuncSetAttribute(gemm_qkv_kernel,    cudaFuncAttributeMaxDynamicSharedMemorySize, SMEM_DYN);
    cudaFuncSetAttribute(gemm_scores_kernel, cudaFuncAttributeMaxDynamicSharedMemorySize, SMEM_DYN);
    cudaFuncSetAttribute(gemm_pv_kernel,     cudaFuncAttributeMaxDynamicSharedMemorySize, SMEM_DYN);

    conv_x_kernel<<<4096, 256>>>(x, out);
    conv_w_kernel<<<dim3(32, 32, 3), 256>>>(Wq, Wk, Wv);
    gemm_qkv_kernel<<<dim3(64, 1, 3), 512, SMEM_DYN>>>(bq, bk, bv);
    gemm_scores_kernel<<<136, 512, SMEM_DYN>>>();
    softmax_kernel<<<SEQ, 256>>>();
    gemm_pv_kernel<<<dim3(4, 16), 512, SMEM_DYN>>>(out);
}

// round 9
// speedup vs baseline: 2.9190x; 2.9190x over previous
#include <cuda_runtime.h>
#include <math.h>
#include <stdint.h>

#define SEQ   4096
#define DIM   1024
#define OUTD  2048
#define SCALE 0.03125f   // 1/sqrt(1024)

#define PADW  68                        // 64 floats + 4 pad per smem row (BK=64)
#define BBUF  (128 * PADW * 4)          // B tile: 34816 B

// ---------------------------------------------------------------------------
// scratch (__device__ globals; no allocations allowed)
// ---------------------------------------------------------------------------
__device__ float g_x [(size_t)SEQ * DIM];          // x, tf32-rounded
__device__ float g_wt[(size_t)3 * DIM * DIM];      // W^T (Q,K,V), tf32-rounded
__device__ float g_q [(size_t)SEQ * DIM];          // tf32-rounded
__device__ float g_k [(size_t)SEQ * DIM];          // tf32-rounded
__device__ float g_vt[(size_t)DIM * SEQ];          // V^T [d][s], tf32-rounded
__device__ float g_s [(size_t)SEQ * SEQ];          // scores fp32
__device__ float g_p [(size_t)SEQ * SEQ];          // probs, tf32-rounded

// ---------------------------------------------------------------------------
// helpers
// ---------------------------------------------------------------------------
__device__ __forceinline__ uint32_t smem_u32(const void* p) {
    uint32_t a;
    asm("{ .reg .u64 t; cvta.to.shared.u64 t, %1; cvt.u32.u64 %0, t; }" : "=r"(a) : "l"(p));
    return a;
}
__device__ __forceinline__ float tf32r(float x) {
    uint32_t u;
    asm("cvt.rna.tf32.f32 %0, %1;" : "=r"(u) : "f"(x));
    return __uint_as_float(u);
}
__device__ __forceinline__ void cp16(uint32_t s, const float* g) {
    asm volatile("{ .reg .u64 gg; cvta.to.global.u64 gg, %1;"
                 "  cp.async.cg.shared.global [%0], [gg], 16; }"
                 :: "r"(s), "l"(g));
}
#define CP_COMMIT() asm volatile("cp.async.commit_group;" ::: "memory")
#define CP_WAIT1()  asm volatile("cp.async.wait_group 1;"  ::: "memory")

__device__ __forceinline__ void ldsm4(uint32_t& r0, uint32_t& r1, uint32_t& r2, uint32_t& r3,
                                      uint32_t addr) {
    asm volatile("ldmatrix.sync.aligned.m8n8.x4.shared.b16 {%0,%1,%2,%3}, [%4];"
                 : "=r"(r0), "=r"(r1), "=r"(r2), "=r"(r3) : "r"(addr));
}

__device__ __forceinline__ void mma8(float* d, const uint32_t* a, const uint32_t* b) {
    asm volatile(
        "mma.sync.aligned.m16n8k8.row.col.f32.tf32.tf32.f32 "
        "{%0,%1,%2,%3}, {%4,%5,%6,%7}, {%8,%9}, {%0,%1,%2,%3};"
        : "+f"(d[0]), "+f"(d[1]), "+f"(d[2]), "+f"(d[3])
        : "r"(a[0]), "r"(a[1]), "r"(a[2]), "r"(a[3]), "r"(b[0]), "r"(b[1]));
}

// ---------------------------------------------------------------------------
// mainloop (512 threads), BK=64 chunks: acc[MT][4][4] += A[MT*64,K] * B[128,K]^T
// 16 warps = 4(m) x 4(n); warp tile (MT*16)x32; tf32 m16n8k8; ldmatrix frags;
// 2-stage cp.async, two syncs per chunk (R6 structure).
// ---------------------------------------------------------------------------
template <int MT>
__device__ __forceinline__ void gemm_mainloop(
    float (*acc)[4][4], char* smem,
    const float* __restrict__ Ag, int lda, int arow0,
    const float* __restrict__ Bg, int ldb, int brow0,
    int kbeg, int kend)
{
    constexpr int AROWS  = MT * 64;
    constexpr int ABUF   = AROWS * PADW * 4;
    constexpr int STAGEB = ABUF + BBUF;

    const int tid  = threadIdx.x;
    const int wid  = tid >> 5, lane = tid & 31;
    const int wm   = (wid & 3) * (MT * 16);
    const int wn   = (wid >> 2) * 32;
    const uint32_t sA = smem_u32(smem);
    const int nch  = (kend - kbeg) >> 6;

    // ldmatrix per-lane base offsets (bytes, within stage)
    const uint32_t aoff = ((wm + (lane & 15)) * PADW + (lane >> 4) * 4) * 4;
    const uint32_t boff = ABUF +
        ((wn + (lane & 7) + ((lane >> 4) & 1) * 8) * PADW + ((lane >> 3) & 1) * 4) * 4;

    // loaders: A = MT*64 rows x 256B, B = 128 rows x 256B
    const int ach = (MT == 4) ? 8 : 4;                 // A cp16 per thread
    const int alm = (MT == 4) ? (tid >> 1) : (tid >> 2);
    const int alq = (MT == 4) ? ((tid & 1) * 8) : ((tid & 3) * 4);
    const int blm = tid >> 2;
    const int blq = (tid & 3) * 4;

#define ISSUE_CHUNK(stg, k0) do {                                              \
    uint32_t _st = sA + (stg) * STAGEB;                                        \
    _Pragma("unroll")                                                          \
    for (int q = 0; q < ach; q++)                                              \
        cp16(_st + (alm * PADW + (alq + q) * 4) * 4,                           \
             Ag + (size_t)(arow0 + alm) * lda + (k0) + (alq + q) * 4);         \
    _Pragma("unroll")                                                          \
    for (int q = 0; q < 4; q++)                                                \
        cp16(_st + ABUF + (blm * PADW + (blq + q) * 4) * 4,                    \
             Bg + (size_t)(brow0 + blm) * ldb + (k0) + (blq + q) * 4);         \
} while (0)

    ISSUE_CHUNK(0, kbeg);
    CP_COMMIT();
    if (nch > 1) ISSUE_CHUNK(1, kbeg + 64);
    CP_COMMIT();

    for (int c = 0; c < nch; c++) {
        CP_WAIT1();
        __syncthreads();
        const uint32_t sb = sA + (c & 1) * STAGEB;
#pragma unroll
        for (int ks = 0; ks < 8; ks++) {
            uint32_t af[MT][4], bf[4][2];
#pragma unroll
            for (int mt = 0; mt < MT; mt++)
                ldsm4(af[mt][0], af[mt][1], af[mt][2], af[mt][3],
                      sb + aoff + mt * (16 * PADW * 4) + ks * 32);
            ldsm4(bf[0][0], bf[0][1], bf[1][0], bf[1][1], sb + boff + ks * 32);
            ldsm4(bf[2][0], bf[2][1], bf[3][0], bf[3][1],
                  sb + boff + 16 * PADW * 4 + ks * 32);
#pragma unroll
            for (int mt = 0; mt < MT; mt++)
#pragma unroll
                for (int nt = 0; nt < 4; nt++)
                    mma8(acc[mt][nt], af[mt], bf[nt]);
        }
        __syncthreads();
        if (c + 2 < nch) ISSUE_CHUNK(c & 1, kbeg + (c + 2) * 64);
        CP_COMMIT();
    }
#undef ISSUE_CHUNK
}

#define GEMM_THREAD_COORDS(MT)                                   \
    const int tid = threadIdx.x;                                 \
    const int wid = tid >> 5, lane = tid & 31;                   \
    const int wm = (wid & 3) * ((MT) * 16), wn = (wid >> 2) * 32;\
    const int r = lane >> 2, cc = lane & 3;

#define ZERO_ACC(acc, MT)                                        \
    float acc[MT][4][4];                                         \
    _Pragma("unroll")                                            \
    for (int i = 0; i < MT; i++)                                 \
        _Pragma("unroll")                                        \
        for (int j = 0; j < 4; j++)                              \
            _Pragma("unroll")                                    \
            for (int q = 0; q < 4; q++) acc[i][j][q] = 0.f;

// ---------------------------------------------------------------------------
// QKV: z=0: Q = x@Wq' + bq ; z=1: K ; z=2: V^T = Wvt @ x^T + bv(row)
// grid (128,1,3): z<2: bi=b>>3 (16 m-tiles of 256), bj=b&7 (8 n-tiles of 128)
//                 z=2: bi=b>>5 (4 m-tiles over DIM), bj=b&31 (32 over SEQ)
// ---------------------------------------------------------------------------
__global__ __launch_bounds__(512, 1) void gemm_qkv_kernel(
    const float* __restrict__ bq, const float* __restrict__ bk, const float* __restrict__ bv)
{
    const int z = blockIdx.z;
    extern __shared__ char smem[];
    const int b = blockIdx.x;
    const int row0 = (z == 2 ? (b >> 5) : (b >> 3)) * 256;
    const int col0 = (z == 2 ? (b & 31) : (b & 7)) * 128;

    ZERO_ACC(acc, 4);

    const float *Ag, *Bg, *bias;
    if (z == 0)      { Ag = g_x;                  Bg = g_wt;             bias = bq; }
    else if (z == 1) { Ag = g_x;                  Bg = g_wt + DIM * DIM; bias = bk; }
    else             { Ag = g_wt + 2 * DIM * DIM; Bg = g_x;              bias = bv; }

    gemm_mainloop<4>(acc, smem, Ag, DIM, row0, Bg, DIM, col0, 0, DIM);

    GEMM_THREAD_COORDS(4);
    float* dst; size_t ld;
    if (z == 0)      { dst = g_q;  ld = DIM; }
    else if (z == 1) { dst = g_k;  ld = DIM; }
    else             { dst = g_vt; ld = SEQ; }

#pragma unroll
    for (int mt = 0; mt < 4; mt++)
#pragma unroll
        for (int h = 0; h < 2; h++) {
            int m = row0 + wm + mt * 16 + r + 8 * h;
            float brow = (z == 2) ? bias[m] : 0.f;
#pragma unroll
            for (int nt = 0; nt < 4; nt++) {
                int n = col0 + wn + nt * 8 + 2 * cc;
                float v0 = acc[mt][nt][2 * h + 0] + ((z == 2) ? brow : bias[n]);
                float v1 = acc[mt][nt][2 * h + 1] + ((z == 2) ? brow : bias[n + 1]);
                float2 w = make_float2(tf32r(v0), tf32r(v1));
                *(float2*)&dst[(size_t)m * ld + n] = w;
            }
        }
}

// ---------------------------------------------------------------------------
// scores: S = SCALE * Q K^T, tiles 256x128; kept iff bj >= 2*bi (272 blocks)
// ---------------------------------------------------------------------------
__global__ __launch_bounds__(512, 1) void gemm_scores_kernel()
{
    int bi = 0, rem = blockIdx.x;
    while (rem >= 32 - 2 * bi) { rem -= 32 - 2 * bi; bi++; }
    const int bj = 2 * bi + rem;

    extern __shared__ char smem[];
    const int row0 = bi * 256, col0 = bj * 128;

    ZERO_ACC(acc, 4);
    gemm_mainloop<4>(acc, smem, g_q, DIM, row0, g_k, DIM, col0, 0, DIM);

    GEMM_THREAD_COORDS(4);
#pragma unroll
    for (int mt = 0; mt < 4; mt++)
#pragma unroll
        for (int h = 0; h < 2; h++) {
            int m = row0 + wm + mt * 16 + r + 8 * h;
#pragma unroll
            for (int nt = 0; nt < 4; nt++) {
                int n = col0 + wn + nt * 8 + 2 * cc;
                float2 w = make_float2(acc[mt][nt][2 * h] * SCALE,
                                       acc[mt][nt][2 * h + 1] * SCALE);
                *(float2*)&g_s[(size_t)m * SEQ + n] = w;
            }
        }
}

// ---------------------------------------------------------------------------
// softmax over j >= i; writes tf32-rounded probs, zero strip in diagonal tile
// ---------------------------------------------------------------------------
__global__ __launch_bounds__(256) void softmax_kernel()
{
    const int i = blockIdx.x;
    const int t = threadIdx.x;
    const float* row = g_s + (size_t)i * SEQ;

    float vals[16];
    float m = -INFINITY;
#pragma unroll
    for (int c = 0; c < 16; c++) {
        int j = t + (c << 8);
        float v = (j >= i) ? row[j] : -INFINITY;
        vals[c] = v;
        m = fmaxf(m, v);
    }
    __shared__ float red[8];
#pragma unroll
    for (int o = 16; o > 0; o >>= 1) m = fmaxf(m, __shfl_xor_sync(0xffffffffu, m, o));
    if ((t & 31) == 0) red[t >> 5] = m;
    __syncthreads();
    float mm = red[0];
#pragma unroll
    for (int w = 1; w < 8; w++) mm = fmaxf(mm, red[w]);
    __syncthreads();

    float sum = 0.f;
#pragma unroll
    for (int c = 0; c < 16; c++) {
        float e = (vals[c] > -INFINITY) ? __expf(vals[c] - mm) : 0.f;
        vals[c] = e;
        sum += e;
    }
#pragma unroll
    for (int o = 16; o > 0; o >>= 1) sum += __shfl_xor_sync(0xffffffffu, sum, o);
    if ((t & 31) == 0) red[t >> 5] = sum;
    __syncthreads();
    float tot = 0.f;
#pragma unroll
    for (int w = 0; w < 8; w++) tot += red[w];
    const float inv = 1.0f / tot;

    const int rowstart = i & ~127;
    float* p = g_p + (size_t)i * SEQ;
#pragma unroll
    for (int c = 0; c < 16; c++) {
        int j = t + (c << 8);
        if (j >= i)             p[j] = tf32r(vals[c] * inv);
        else if (j >= rowstart) p[j] = 0.f;
    }
}

// ---------------------------------------------------------------------------
// PV: read = P @ V ; tiles 128x128 (MT=2); k starts at the diagonal 128-tile.
// grid (8, 32): row0 = y*128, col0 = x*128
// ---------------------------------------------------------------------------
__global__ __launch_bounds__(512, 1) void gemm_pv_kernel(float* __restrict__ out)
{
    extern __shared__ char smem[];
    const int row0 = blockIdx.y * 128, col0 = blockIdx.x * 128;

    ZERO_ACC(acc, 2);
    gemm_mainloop<2>(acc, smem, g_p, SEQ, row0, g_vt, SEQ, col0, row0 & ~63, SEQ);

    GEMM_THREAD_COORDS(2);
#pragma unroll
    for (int mt = 0; mt < 2; mt++)
#pragma unroll
        for (int h = 0; h < 2; h++) {
            int m = row0 + wm + mt * 16 + r + 8 * h;
#pragma unroll
            for (int nt = 0; nt < 4; nt++) {
                int n = col0 + wn + nt * 8 + 2 * cc;
                float2 w = make_float2(acc[mt][nt][2 * h], acc[mt][nt][2 * h + 1]);
                *(float2*)&out[(size_t)m * OUTD + DIM + n] = w;
            }
        }
}

// ---------------------------------------------------------------------------
// conversions
// ---------------------------------------------------------------------------
__global__ __launch_bounds__(256) void conv_x_kernel(const float* __restrict__ x,
                                                     float* __restrict__ out)
{
    int idx = blockIdx.x * 256 + threadIdx.x;   // float4 index
    int r = idx >> 8;
    int c = (idx & 255) * 4;
    float4 v = *(const float4*)&x[(size_t)r * DIM + c];
    *(float4*)&out[(size_t)r * OUTD + c] = v;   // out[:, 0:1024] = x
    float4 w = make_float4(tf32r(v.x), tf32r(v.y), tf32r(v.z), tf32r(v.w));
    *(float4*)&g_x[(size_t)r * DIM + c] = w;
}

// transpose + tf32-round W [k][n] -> Wt [n][k] (slot z: 0=Q, 1=K, 2=V)
__global__ __launch_bounds__(256) void conv_w_kernel(const float* __restrict__ Wq,
                                                     const float* __restrict__ Wk,
                                                     const float* __restrict__ Wv)
{
    __shared__ float t[32][33];
    const int z = blockIdx.z;
    const float* W = (z == 0) ? Wq : (z == 1) ? Wk : Wv;
    const int n0 = blockIdx.x * 32, k0 = blockIdx.y * 32;
    const int tx = threadIdx.x & 31, ty = threadIdx.x >> 5;
#pragma unroll
    for (int i = 0; i < 4; i++) {
        int k = ty + i * 8;
        t[k][tx] = W[(size_t)(k0 + k) * DIM + n0 + tx];
    }
    __syncthreads();
    float* T = g_wt + (size_t)z * DIM * DIM;
#pragma unroll
    for (int i = 0; i < 4; i++) {
        int n = ty + i * 8;
        T[(size_t)(n0 + n) * DIM + k0 + tx] = tf32r(t[tx][n]);
    }
}

// ---------------------------------------------------------------------------
extern "C" void kernel_launch(void* const* d_in, const int* in_sizes, int n_in,
                              void* d_out, int out_size)
{
    const float* x  = (const float*)d_in[0];
    const float* Wk = (const float*)d_in[1];
    const float* bk = (const float*)d_in[2];
    const float* Wq = (const float*)d_in[3];
    const float* bq = (const float*)d_in[4];
    const float* Wv = (const float*)d_in[5];
    const float* bv = (const float*)d_in[6];
    float* out = (float*)d_out;

    const int SM4 = 2 * (256 * PADW * 4 + BBUF);   // 208896
    const int SM2 = 2 * (128 * PADW * 4 + BBUF);   // 139264

    cudaFuncSetAttribute(gemm_qkv_kernel,    cudaFuncAttributeMaxDynamicSharedMemorySize, SM4);
    cudaFuncSetAttribute(gemm_scores_kernel, cudaFuncAttributeMaxDynamicSharedMemorySize, SM4);
    cudaFuncSetAttribute(gemm_pv_kernel,     cudaFuncAttributeMaxDynamicSharedMemorySize, SM2);

    conv_x_kernel<<<4096, 256>>>(x, out);
    conv_w_kernel<<<dim3(32, 32, 3), 256>>>(Wq, Wk, Wv);
    gemm_qkv_kernel<<<dim3(128, 1, 3), 512, SM4>>>(bq, bk, bv);
    gemm_scores_kernel<<<272, 512, SM4>>>();
    softmax_kernel<<<SEQ, 256>>>();
    gemm_pv_kernel<<<dim3(8, 32), 512, SM2>>>(out);
}

// round 10
// speedup vs baseline: 7.2895x; 2.4972x over previous
#include <cuda_runtime.h>
#include <cuda_fp16.h>
#include <math.h>
#include <stdint.h>

#define SEQ   4096
#define DIM   1024
#define OUTD  2048
#define SCALE 0.03125f   // 1/sqrt(1024)

#define PADH  40                        // 32 halves + 8 pad per smem row (80 B)
#define BBUF  (128 * PADH * 2)          // B tile: 10240 B

// ---------------------------------------------------------------------------
// scratch (__device__ globals; no allocations allowed)
// ---------------------------------------------------------------------------
__device__ __half g_x [(size_t)SEQ * DIM];          // x (fp16)
__device__ __half g_wt[(size_t)3 * DIM * DIM];      // W^T (Q,K,V) (fp16)
__device__ __half g_q [(size_t)SEQ * DIM];
__device__ __half g_k [(size_t)SEQ * DIM];
__device__ __half g_vt[(size_t)DIM * SEQ];          // V^T [d][s]
__device__ float  g_s [(size_t)SEQ * SEQ];          // scores fp32
__device__ __half g_p [(size_t)SEQ * SEQ];          // probs (fp16)

// ---------------------------------------------------------------------------
// helpers
// ---------------------------------------------------------------------------
__device__ __forceinline__ uint32_t smem_u32(const void* p) {
    uint32_t a;
    asm("{ .reg .u64 t; cvta.to.shared.u64 t, %1; cvt.u32.u64 %0, t; }" : "=r"(a) : "l"(p));
    return a;
}
__device__ __forceinline__ void cp16(uint32_t s, const void* g) {
    asm volatile("{ .reg .u64 gg; cvta.to.global.u64 gg, %1;"
                 "  cp.async.cg.shared.global [%0], [gg], 16; }"
                 :: "r"(s), "l"(g));
}
#define CP_COMMIT() asm volatile("cp.async.commit_group;" ::: "memory")
#define CP_WAIT1()  asm volatile("cp.async.wait_group 1;"  ::: "memory")

__device__ __forceinline__ void ldsm4(uint32_t& r0, uint32_t& r1, uint32_t& r2, uint32_t& r3,
                                      uint32_t addr) {
    asm volatile("ldmatrix.sync.aligned.m8n8.x4.shared.b16 {%0,%1,%2,%3}, [%4];"
                 : "=r"(r0), "=r"(r1), "=r"(r2), "=r"(r3) : "r"(addr));
}

// fp16 MMA: D(f32) += A(f16) * B(f16), m16n8k16
__device__ __forceinline__ void mma16(float* d, const uint32_t* a, const uint32_t* b) {
    asm volatile(
        "mma.sync.aligned.m16n8k16.row.col.f32.f16.f16.f32 "
        "{%0,%1,%2,%3}, {%4,%5,%6,%7}, {%8,%9}, {%0,%1,%2,%3};"
        : "+f"(d[0]), "+f"(d[1]), "+f"(d[2]), "+f"(d[3])
        : "r"(a[0]), "r"(a[1]), "r"(a[2]), "r"(a[3]), "r"(b[0]), "r"(b[1]));
}

// ---------------------------------------------------------------------------
// mainloop (512 threads), fp16, BK=32: acc[MT][4][4] += A[MT*64,K] * B[128,K]^T
// 16 warps = 4(m) x 4(n); warp tile (MT*16)x32; m16n8k16; ldmatrix frags;
// 2-stage cp.async, two syncs per chunk (R6 structure).
// ---------------------------------------------------------------------------
template <int MT>
__device__ __forceinline__ void gemm_mainloop(
    float (*acc)[4][4], char* smem,
    const __half* __restrict__ Ag, int lda, int arow0,
    const __half* __restrict__ Bg, int ldb, int brow0,
    int kbeg, int kend)
{
    constexpr int AROWS  = MT * 64;
    constexpr int ABUF   = AROWS * PADH * 2;
    constexpr int STAGEB = ABUF + BBUF;

    const int tid  = threadIdx.x;
    const int wid  = tid >> 5, lane = tid & 31;
    const int wm   = (wid & 3) * (MT * 16);
    const int wn   = (wid >> 2) * 32;
    const uint32_t sA = smem_u32(smem);
    const int nch  = (kend - kbeg) >> 5;

    // ldmatrix per-lane base offsets (bytes, within stage)
    const uint32_t aoff = ((wm + (lane & 15)) * PADH + (lane >> 4) * 8) * 2;
    const uint32_t boff = ABUF +
        ((wn + (lane & 7) + ((lane >> 4) & 1) * 8) * PADH + ((lane >> 3) & 1) * 8) * 2;

    // loaders: rows of 64 B data (4 x 16 B chunks)
    const int ach = (MT == 4) ? 2 : 1;                 // A cp16 per thread
    const int alm = (MT == 4) ? (tid >> 1) : (tid >> 2);
    const int alq = (MT == 4) ? ((tid & 1) * 2) : (tid & 3);
    const int blm = tid >> 2;
    const int blq = tid & 3;

#define ISSUE_CHUNK(stg, k0) do {                                              \
    uint32_t _st = sA + (stg) * STAGEB;                                        \
    _Pragma("unroll")                                                          \
    for (int q = 0; q < ach; q++)                                              \
        cp16(_st + (alm * PADH + (alq + q) * 8) * 2,                           \
             Ag + (size_t)(arow0 + alm) * lda + (k0) + (alq + q) * 8);         \
    cp16(_st + ABUF + (blm * PADH + blq * 8) * 2,                              \
         Bg + (size_t)(brow0 + blm) * ldb + (k0) + blq * 8);                   \
} while (0)

    ISSUE_CHUNK(0, kbeg);
    CP_COMMIT();
    if (nch > 1) ISSUE_CHUNK(1, kbeg + 32);
    CP_COMMIT();

    for (int c = 0; c < nch; c++) {
        CP_WAIT1();
        __syncthreads();
        const uint32_t sb = sA + (c & 1) * STAGEB;
#pragma unroll
        for (int ks = 0; ks < 2; ks++) {          // two k16 steps per 32-chunk
            uint32_t af[MT][4], bf[4][2];
#pragma unroll
            for (int mt = 0; mt < MT; mt++)
                ldsm4(af[mt][0], af[mt][1], af[mt][2], af[mt][3],
                      sb + aoff + mt * (16 * PADH * 2) + ks * 32);
            ldsm4(bf[0][0], bf[0][1], bf[1][0], bf[1][1], sb + boff + ks * 32);
            ldsm4(bf[2][0], bf[2][1], bf[3][0], bf[3][1],
                  sb + boff + 16 * PADH * 2 + ks * 32);
#pragma unroll
            for (int mt = 0; mt < MT; mt++)
#pragma unroll
                for (int nt = 0; nt < 4; nt++)
                    mma16(acc[mt][nt], af[mt], bf[nt]);
        }
        __syncthreads();
        if (c + 2 < nch) ISSUE_CHUNK(c & 1, kbeg + (c + 2) * 32);
        CP_COMMIT();
    }
#undef ISSUE_CHUNK
}

#define GEMM_THREAD_COORDS(MT)                                   \
    const int tid = threadIdx.x;                                 \
    const int wid = tid >> 5, lane = tid & 31;                   \
    const int wm = (wid & 3) * ((MT) * 16), wn = (wid >> 2) * 32;\
    const int r = lane >> 2, cc = lane & 3;

#define ZERO_ACC(acc, MT)                                        \
    float acc[MT][4][4];                                         \
    _Pragma("unroll")                                            \
    for (int i = 0; i < MT; i++)                                 \
        _Pragma("unroll")                                        \
        for (int j = 0; j < 4; j++)                              \
            _Pragma("unroll")                                    \
            for (int q = 0; q < 4; q++) acc[i][j][q] = 0.f;

// ---------------------------------------------------------------------------
// QKV: z=0: Q = x@Wq' + bq ; z=1: K ; z=2: V^T = Wvt @ x^T + bv(row)
// grid (128,1,3): z<2: bi=b>>3 (16 m-tiles of 256), bj=b&7 (8 n-tiles of 128)
//                 z=2: bi=b>>5 (4 m-tiles over DIM), bj=b&31 (32 over SEQ)
// ---------------------------------------------------------------------------
__global__ __launch_bounds__(512, 1) void gemm_qkv_kernel(
    const float* __restrict__ bq, const float* __restrict__ bk, const float* __restrict__ bv)
{
    const int z = blockIdx.z;
    extern __shared__ char smem[];
    const int b = blockIdx.x;
    const int row0 = (z == 2 ? (b >> 5) : (b >> 3)) * 256;
    const int col0 = (z == 2 ? (b & 31) : (b & 7)) * 128;

    ZERO_ACC(acc, 4);

    const __half *Ag, *Bg;
    const float* bias;
    if (z == 0)      { Ag = g_x;                  Bg = g_wt;             bias = bq; }
    else if (z == 1) { Ag = g_x;                  Bg = g_wt + DIM * DIM; bias = bk; }
    else             { Ag = g_wt + 2 * DIM * DIM; Bg = g_x;              bias = bv; }

    gemm_mainloop<4>(acc, smem, Ag, DIM, row0, Bg, DIM, col0, 0, DIM);

    GEMM_THREAD_COORDS(4);
    __half* dst; size_t ld;
    if (z == 0)      { dst = g_q;  ld = DIM; }
    else if (z == 1) { dst = g_k;  ld = DIM; }
    else             { dst = g_vt; ld = SEQ; }

#pragma unroll
    for (int mt = 0; mt < 4; mt++)
#pragma unroll
        for (int h = 0; h < 2; h++) {
            int m = row0 + wm + mt * 16 + r + 8 * h;
            float brow = (z == 2) ? bias[m] : 0.f;
#pragma unroll
            for (int nt = 0; nt < 4; nt++) {
                int n = col0 + wn + nt * 8 + 2 * cc;
                float v0 = acc[mt][nt][2 * h + 0] + ((z == 2) ? brow : bias[n]);
                float v1 = acc[mt][nt][2 * h + 1] + ((z == 2) ? brow : bias[n + 1]);
                *(__half2*)&dst[(size_t)m * ld + n] = __floats2half2_rn(v0, v1);
            }
        }
}

// ---------------------------------------------------------------------------
// scores: S = SCALE * Q K^T, tiles 256x128; kept iff bj >= 2*bi (272 blocks)
// ---------------------------------------------------------------------------
__global__ __launch_bounds__(512, 1) void gemm_scores_kernel()
{
    int bi = 0, rem = blockIdx.x;
    while (rem >= 32 - 2 * bi) { rem -= 32 - 2 * bi; bi++; }
    const int bj = 2 * bi + rem;

    extern __shared__ char smem[];
    const int row0 = bi * 256, col0 = bj * 128;

    ZERO_ACC(acc, 4);
    gemm_mainloop<4>(acc, smem, g_q, DIM, row0, g_k, DIM, col0, 0, DIM);

    GEMM_THREAD_COORDS(4);
#pragma unroll
    for (int mt = 0; mt < 4; mt++)
#pragma unroll
        for (int h = 0; h < 2; h++) {
            int m = row0 + wm + mt * 16 + r + 8 * h;
#pragma unroll
            for (int nt = 0; nt < 4; nt++) {
                int n = col0 + wn + nt * 8 + 2 * cc;
                float2 w = make_float2(acc[mt][nt][2 * h] * SCALE,
                                       acc[mt][nt][2 * h + 1] * SCALE);
                *(float2*)&g_s[(size_t)m * SEQ + n] = w;
            }
        }
}

// ---------------------------------------------------------------------------
// softmax over j >= i; writes fp16 probs, zero strip in diagonal tile
// ---------------------------------------------------------------------------
__global__ __launch_bounds__(256) void softmax_kernel()
{
    const int i = blockIdx.x;
    const int t = threadIdx.x;
    const float* row = g_s + (size_t)i * SEQ;

    float vals[16];
    float m = -INFINITY;
#pragma unroll
    for (int c = 0; c < 16; c++) {
        int j = t + (c << 8);
        float v = (j >= i) ? row[j] : -INFINITY;
        vals[c] = v;
        m = fmaxf(m, v);
    }
    __shared__ float red[8];
#pragma unroll
    for (int o = 16; o > 0; o >>= 1) m = fmaxf(m, __shfl_xor_sync(0xffffffffu, m, o));
    if ((t & 31) == 0) red[t >> 5] = m;
    __syncthreads();
    float mm = red[0];
#pragma unroll
    for (int w = 1; w < 8; w++) mm = fmaxf(mm, red[w]);
    __syncthreads();

    float sum = 0.f;
#pragma unroll
    for (int c = 0; c < 16; c++) {
        float e = (vals[c] > -INFINITY) ? __expf(vals[c] - mm) : 0.f;
        vals[c] = e;
        sum += e;
    }
#pragma unroll
    for (int o = 16; o > 0; o >>= 1) sum += __shfl_xor_sync(0xffffffffu, sum, o);
    if ((t & 31) == 0) red[t >> 5] = sum;
    __syncthreads();
    float tot = 0.f;
#pragma unroll
    for (int w = 0; w < 8; w++) tot += red[w];
    const float inv = 1.0f / tot;

    const int rowstart = i & ~127;
    __half* p = g_p + (size_t)i * SEQ;
#pragma unroll
    for (int c = 0; c < 16; c++) {
        int j = t + (c << 8);
        if (j >= i)             p[j] = __float2half(vals[c] * inv);
        else if (j >= rowstart) p[j] = __float2half(0.f);
    }
}

// ---------------------------------------------------------------------------
// PV: read = P @ V ; tiles 128x128 (MT=2); k starts at the diagonal 128-tile.
// grid (8, 32): row0 = y*128, col0 = x*128
// ---------------------------------------------------------------------------
__global__ __launch_bounds__(512, 1) void gemm_pv_kernel(float* __restrict__ out)
{
    extern __shared__ char smem[];
    const int row0 = blockIdx.y * 128, col0 = blockIdx.x * 128;

    ZERO_ACC(acc, 2);
    gemm_mainloop<2>(acc, smem, g_p, SEQ, row0, g_vt, SEQ, col0, row0, SEQ);

    GEMM_THREAD_COORDS(2);
#pragma unroll
    for (int mt = 0; mt < 2; mt++)
#pragma unroll
        for (int h = 0; h < 2; h++) {
            int m = row0 + wm + mt * 16 + r + 8 * h;
#pragma unroll
            for (int nt = 0; nt < 4; nt++) {
                int n = col0 + wn + nt * 8 + 2 * cc;
                float2 w = make_float2(acc[mt][nt][2 * h], acc[mt][nt][2 * h + 1]);
                *(float2*)&out[(size_t)m * OUTD + DIM + n] = w;
            }
        }
}

// ---------------------------------------------------------------------------
// conversions
// ---------------------------------------------------------------------------
__global__ __launch_bounds__(256) void conv_x_kernel(const float* __restrict__ x,
                                                     float* __restrict__ out)
{
    int idx = blockIdx.x * 256 + threadIdx.x;   // float4 index
    int r = idx >> 8;
    int c = (idx & 255) * 4;
    float4 v = *(const float4*)&x[(size_t)r * DIM + c];
    *(float4*)&out[(size_t)r * OUTD + c] = v;   // out[:, 0:1024] = x
    __half2 h0 = __floats2half2_rn(v.x, v.y);
    __half2 h1 = __floats2half2_rn(v.z, v.w);
    *(__half2*)&g_x[(size_t)r * DIM + c]     = h0;
    *(__half2*)&g_x[(size_t)r * DIM + c + 2] = h1;
}

// transpose + fp16-convert W [k][n] -> Wt [n][k] (slot z: 0=Q, 1=K, 2=V)
__global__ __launch_bounds__(256) void conv_w_kernel(const float* __restrict__ Wq,
                                                     const float* __restrict__ Wk,
                                                     const float* __restrict__ Wv)
{
    __shared__ float t[32][33];
    const int z = blockIdx.z;
    const float* W = (z == 0) ? Wq : (z == 1) ? Wk : Wv;
    const int n0 = blockIdx.x * 32, k0 = blockIdx.y * 32;
    const int tx = threadIdx.x & 31, ty = threadIdx.x >> 5;
#pragma unroll
    for (int i = 0; i < 4; i++) {
        int k = ty + i * 8;
        t[k][tx] = W[(size_t)(k0 + k) * DIM + n0 + tx];
    }
    __syncthreads();
    __half* T = g_wt + (size_t)z * DIM * DIM;
#pragma unroll
    for (int i = 0; i < 4; i++) {
        int n = ty + i * 8;
        T[(size_t)(n0 + n) * DIM + k0 + tx] = __float2half(t[tx][n]);
    }
}

// ---------------------------------------------------------------------------
extern "C" void kernel_launch(void* const* d_in, const int* in_sizes, int n_in,
                              void* d_out, int out_size)
{
    const float* x  = (const float*)d_in[0];
    const float* Wk = (const float*)d_in[1];
    const float* bk = (const float*)d_in[2];
    const float* Wq = (const float*)d_in[3];
    const float* bq = (const float*)d_in[4];
    const float* Wv = (const float*)d_in[5];
    const float* bv = (const float*)d_in[6];
    float* out = (float*)d_out;

    const int SM4 = 2 * (256 * PADH * 2 + BBUF);   // 61440
    const int SM2 = 2 * (128 * PADH * 2 + BBUF);   // 40960

    cudaFuncSetAttribute(gemm_qkv_kernel,    cudaFuncAttributeMaxDynamicSharedMemorySize, SM4);
    cudaFuncSetAttribute(gemm_scores_kernel, cudaFuncAttributeMaxDynamicSharedMemorySize, SM4);
    cudaFuncSetAttribute(gemm_pv_kernel,     cudaFuncAttributeMaxDynamicSharedMemorySize, SM2);

    conv_x_kernel<<<4096, 256>>>(x, out);
    conv_w_kernel<<<dim3(32, 32, 3), 256>>>(Wq, Wk, Wv);
    gemm_qkv_kernel<<<dim3(128, 1, 3), 512, SM4>>>(bq, bk, bv);
    gemm_scores_kernel<<<272, 512, SM4>>>();
    softmax_kernel<<<SEQ, 256>>>();
    gemm_pv_kernel<<<dim3(8, 32), 512, SM2>>>(out);
}